// round 8
// baseline (speedup 1.0000x reference)
#include <cuda_runtime.h>

// ---------------- problem-size constants (fixed by the dataset) -------------
#define NMAX 100000
#define EMAX 3200000
#define PAD  128          // max in-degree slot (deg ~ Binomial, mean 32, std 5.7)

// ---------------- device scratch (no allocations allowed) -------------------
__device__ int    g_cursor[NMAX];        // per-node CSR write cursor
__device__ int    g_csr[NMAX * PAD];     // padded CSR: sources of in-edges of node v
__device__ float  g_dinv[NMAX];          // rsqrt(deg+1)
__device__ float2 g_y[NMAX];             // y[v] = x[v] * dinv[v]
__device__ float2 g_s2[NMAX];            // s2[v] = (h[v]@W2) * dinv[v]
__device__ float4 g_pA[NMAX];            // pA[v] = h[v] @ We[0:16]
__device__ float4 g_pB[NMAX];            // pB[v] = h[v] @ We[17:33]
__device__ int    g_idx64;               // 1 if edge_index is int64

// composed linear coefficients (epilogue of layer 1 is linear in (ax,ay))
__device__ float  g_M2[4], g_c2[2];      // W1@W2 (2x2), b1@W2
__device__ float  g_MA[8], g_cA[4];      // W1@We[0:16] (2x4), b1@We[0:16]
__device__ float  g_MB[8], g_cB[4];      // W1@We[17:33] (2x4), b1@We[17:33]

__device__ __forceinline__ int load_idx(const void* base, long long i, int is64) {
    if (is64) return (int)__ldg(((const long long*)base) + i);
    return __ldg(((const int*)base) + i);
}

// ---------------- K0: init cursors + idx-width detect + compose matrices -----
__global__ void k_init(const int* __restrict__ p, int n,
                       const float* __restrict__ W1, const float* __restrict__ b1,
                       const float* __restrict__ We, const float* __restrict__ W2) {
    int v = blockIdx.x * blockDim.x + threadIdx.x;
    if (v < n) g_cursor[v] = v * PAD;
    if (blockIdx.x == 0) {
        int t = threadIdx.x;
        if (t == 31) {                       // index width probe
            int f = 1;
            #pragma unroll 1
            for (int i = 0; i < 64; i++) {
                if (p[2 * i + 1] != 0) { f = 0; break; }
            }
            g_idx64 = f;
        }
        // composed projection coefficients (30 tiny dot products)
        if (t < 4) {                         // M2[i*2+j] = sum_q W1[i,q] W2[q,j]
            int i = t >> 1, j = t & 1;
            float s = 0.f;
            #pragma unroll
            for (int q = 0; q < 16; q++) s += W1[i * 16 + q] * W2[q * 2 + j];
            g_M2[t] = s;
        } else if (t < 6) {                  // c2[j]
            int j = t - 4;
            float s = 0.f;
            #pragma unroll
            for (int q = 0; q < 16; q++) s += b1[q] * W2[q * 2 + j];
            g_c2[j] = s;
        } else if (t < 14) {                 // MA[i*4+j]
            int u = t - 6, i = u >> 2, j = u & 3;
            float s = 0.f;
            #pragma unroll
            for (int q = 0; q < 16; q++) s += W1[i * 16 + q] * We[q * 4 + j];
            g_MA[u] = s;
        } else if (t < 18) {                 // cA[j]
            int j = t - 14;
            float s = 0.f;
            #pragma unroll
            for (int q = 0; q < 16; q++) s += b1[q] * We[q * 4 + j];
            g_cA[j] = s;
        } else if (t < 26) {                 // MB[i*4+j]
            int u = t - 18, i = u >> 2, j = u & 3;
            float s = 0.f;
            #pragma unroll
            for (int q = 0; q < 16; q++) s += W1[i * 16 + q] * We[(17 + q) * 4 + j];
            g_MB[u] = s;
        } else if (t < 30) {                 // cB[j]
            int j = t - 26;
            float s = 0.f;
            #pragma unroll
            for (int q = 0; q < 16; q++) s += b1[q] * We[(17 + q) * 4 + j];
            g_cB[j] = s;
        }
    }
}

// ---------------- K1: build padded CSR (1 int atomic per edge) ---------------
__global__ void k_build(const void* __restrict__ ei, int E) {
    int e = blockIdx.x * blockDim.x + threadIdx.x;
    if (e >= E) return;
    int is64 = g_idx64;
    int r = load_idx(ei, e, is64);
    int c = load_idx(ei, (long long)E + e, is64);
    int p = atomicAdd(&g_cursor[c], 1);
    if (p < c * PAD + PAD) g_csr[p] = r;
}

// ---------------- K2: per-node dinv + y = x*dinv -----------------------------
__global__ void k_node1(const float* __restrict__ x, int n) {
    int v = blockIdx.x * blockDim.x + threadIdx.x;
    if (v >= n) return;
    int deg = g_cursor[v] - v * PAD;
    float dinv = rsqrtf((float)(deg + 1));
    g_dinv[v] = dinv;
    float2 xv = ((const float2*)x)[v];
    g_y[v] = make_float2(xv.x * dinv, xv.y * dinv);
}

// ---------------- K3: aggregate y (2-dim), composed epilogue -----------------
__global__ void k_agg1(int n) {
    int t = threadIdx.x;
    int v = (blockIdx.x * blockDim.x + t) >> 5;
    if (v >= n) return;
    int lane = t & 31;
    int start = v * PAD;
    int end = min(g_cursor[v], start + PAD);

    float dv = g_dinv[v];
    float2 yv = g_y[v];

    float ax = 0.f, ay = 0.f;
    for (int p = start + lane; p < end; p += 32) {
        float2 yu = g_y[__ldg(&g_csr[p])];
        ax += yu.x; ay += yu.y;
    }
    #pragma unroll
    for (int off = 16; off; off >>= 1) {
        ax += __shfl_xor_sync(0xffffffffu, ax, off);
        ay += __shfl_xor_sync(0xffffffffu, ay, off);
    }

    if (lane == 0) {
        ax += yv.x; ay += yv.y;          // self-loop
        float d2 = dv * dv;
        float2 s2;
        s2.x = d2 * (ax * g_M2[0] + ay * g_M2[2]) + dv * g_c2[0];
        s2.y = d2 * (ax * g_M2[1] + ay * g_M2[3]) + dv * g_c2[1];
        g_s2[v] = s2;
        float4 pa, pb;
        pa.x = dv * (ax * g_MA[0] + ay * g_MA[4]) + g_cA[0];
        pa.y = dv * (ax * g_MA[1] + ay * g_MA[5]) + g_cA[1];
        pa.z = dv * (ax * g_MA[2] + ay * g_MA[6]) + g_cA[2];
        pa.w = dv * (ax * g_MA[3] + ay * g_MA[7]) + g_cA[3];
        g_pA[v] = pa;
        pb.x = dv * (ax * g_MB[0] + ay * g_MB[4]) + g_cB[0];
        pb.y = dv * (ax * g_MB[1] + ay * g_MB[5]) + g_cB[1];
        pb.z = dv * (ax * g_MB[2] + ay * g_MB[6]) + g_cB[2];
        pb.w = dv * (ax * g_MB[3] + ay * g_MB[7]) + g_cB[3];
        g_pB[v] = pb;
    }
}

// ---------------- K4: FUSED tail — edge MLP (blocks [0,edgeBlocks)) ----------
//                        + layer-2 aggregate/softmax (blocks after) -----------
// The two halves are independent (both consume only k_agg1 outputs + CSR) and
// write disjoint output regions, so one launch overlaps them on the chip.
__global__ void k_tail(const void* __restrict__ ei, const float* __restrict__ ea,
                       const float* __restrict__ We, const float* __restrict__ be,
                       const float* __restrict__ b2,
                       float* __restrict__ outN, float* __restrict__ outE,
                       int n, int E, int edgeBlocks) {
    int t = threadIdx.x;
    if ((int)blockIdx.x < edgeBlocks) {
        // ---- edge MLP + log_softmax ----
        int e = blockIdx.x * blockDim.x + t;
        if (e >= E) return;
        int is64 = g_idx64;
        int r = load_idx(ei, e, is64);
        int c = load_idx(ei, (long long)E + e, is64);
        float a = __ldg(&ea[e]);
        float4 pa = g_pA[r];
        float4 pb = g_pB[c];
        float t0 = pa.x + pb.x + a * __ldg(&We[64 + 0]) + __ldg(&be[0]);
        float t1 = pa.y + pb.y + a * __ldg(&We[64 + 1]) + __ldg(&be[1]);
        float t2 = pa.z + pb.z + a * __ldg(&We[64 + 2]) + __ldg(&be[2]);
        float t3 = pa.w + pb.w + a * __ldg(&We[64 + 3]) + __ldg(&be[3]);
        t0 = fmaxf(t0, 0.f); t1 = fmaxf(t1, 0.f);
        t2 = fmaxf(t2, 0.f); t3 = fmaxf(t3, 0.f);
        float m = fmaxf(fmaxf(t0, t1), fmaxf(t2, t3));
        float s = expf(t0 - m) + expf(t1 - m) + expf(t2 - m) + expf(t3 - m);
        float l = m + logf(s);
        ((float4*)outE)[e] = make_float4(t0 - l, t1 - l, t2 - l, t3 - l);
    } else {
        // ---- layer-2 aggregate + node log_softmax (warp per node) ----
        int v = ((blockIdx.x - edgeBlocks) * blockDim.x + t) >> 5;
        if (v >= n) return;
        int lane = t & 31;
        int start = v * PAD;
        int end = min(g_cursor[v], start + PAD);
        float dv = g_dinv[v];
        float2 sv = g_s2[v];
        float a0 = 0.f, a1 = 0.f;
        for (int p = start + lane; p < end; p += 32) {
            float2 s = g_s2[__ldg(&g_csr[p])];
            a0 += s.x; a1 += s.y;
        }
        #pragma unroll
        for (int off = 16; off; off >>= 1) {
            a0 += __shfl_xor_sync(0xffffffffu, a0, off);
            a1 += __shfl_xor_sync(0xffffffffu, a1, off);
        }
        if (lane == 0) {
            float o0 = dv * (a0 + sv.x) + __ldg(&b2[0]);
            float o1 = dv * (a1 + sv.y) + __ldg(&b2[1]);
            float m = fmaxf(o0, o1);
            float l = logf(expf(o0 - m) + expf(o1 - m));
            ((float2*)outN)[v] = make_float2(o0 - m - l, o1 - m - l);
        }
    }
}

// ---------------- launch ------------------------------------------------------
extern "C" void kernel_launch(void* const* d_in, const int* in_sizes, int n_in,
                              void* d_out, int out_size) {
    const float* x  = (const float*)d_in[0];
    const void*  ei = d_in[1];
    const float* ea = (const float*)d_in[2];
    const float* W1 = (const float*)d_in[3];
    const float* b1 = (const float*)d_in[4];
    const float* We = (const float*)d_in[5];
    const float* be = (const float*)d_in[6];
    const float* W2 = (const float*)d_in[7];
    const float* b2 = (const float*)d_in[8];

    int n = in_sizes[0] / 2;
    int E = in_sizes[1] / 2;
    float* outN = (float*)d_out;
    float* outE = outN + 2 * (size_t)n;

    const int TB = 256;
    const int warpsPerBlk = TB / 32;
    int edgeBlocks = (E + TB - 1) / TB;
    int nodeBlocks = (n + warpsPerBlk - 1) / warpsPerBlk;

    k_init  <<<(n + TB - 1) / TB, TB>>>((const int*)ei, n, W1, b1, We, W2);
    k_build <<<(E + TB - 1) / TB, TB>>>(ei, E);
    k_node1 <<<(n + TB - 1) / TB, TB>>>(x, n);
    k_agg1  <<<nodeBlocks, TB>>>(n);
    k_tail  <<<edgeBlocks + nodeBlocks, TB>>>(ei, ea, We, be, b2, outN, outE, n, E, edgeBlocks);
}

// round 13
// speedup vs baseline: 1.1505x; 1.1505x over previous
#include <cuda_runtime.h>

// ---------------- problem-size constants (fixed by the dataset) -------------
#define NMAX 100000
#define EMAX 3200000
#define PAD  128          // max in-degree slot (deg ~ Binomial, mean 32, std 5.7)

// ---------------- device scratch (no allocations allowed) -------------------
__device__ int    g_cursor[NMAX];        // per-node CSR write cursor
__device__ int    g_csr[NMAX * PAD];     // padded CSR: sources of in-edges of node v
__device__ float  g_dinv[NMAX];          // rsqrt(deg+1)
__device__ float2 g_y[NMAX];             // y[v] = x[v] * dinv[v]
__device__ float2 g_s2[NMAX];            // s2[v] = (h[v]@W2) * dinv[v]
__device__ float4 g_pA[NMAX];            // pA[v] = h[v] @ We[0:16]
__device__ float4 g_pB[NMAX];            // pB[v] = h[v] @ We[17:33]
__device__ int    g_idx64;               // 1 if edge_index is int64

// composed linear coefficients (epilogue of layer 1 is linear in (ax,ay))
__device__ float  g_M2[4], g_c2[2];      // W1@W2 (2x2), b1@W2
__device__ float  g_MA[8], g_cA[4];      // W1@We[0:16] (2x4), b1@We[0:16]
__device__ float  g_MB[8], g_cB[4];      // W1@We[17:33] (2x4), b1@We[17:33]

__device__ __forceinline__ int load_idx(const void* base, long long i, int is64) {
    if (is64) return (int)__ldg(((const long long*)base) + i);
    return __ldg(((const int*)base) + i);
}

// ---------------- K0: init cursors + idx-width detect + compose matrices -----
__global__ void k_init(const int* __restrict__ p, int n,
                       const float* __restrict__ W1, const float* __restrict__ b1,
                       const float* __restrict__ We, const float* __restrict__ W2) {
    int v = blockIdx.x * blockDim.x + threadIdx.x;
    if (v < n) g_cursor[v] = v * PAD;
    if (blockIdx.x == 0) {
        int t = threadIdx.x;
        if (t == 31) {                       // index width probe
            int f = 1;
            #pragma unroll 1
            for (int i = 0; i < 64; i++) {
                if (p[2 * i + 1] != 0) { f = 0; break; }
            }
            g_idx64 = f;
        }
        if (t < 4) {                         // M2[i*2+j]
            int i = t >> 1, j = t & 1;
            float s = 0.f;
            #pragma unroll
            for (int q = 0; q < 16; q++) s += W1[i * 16 + q] * W2[q * 2 + j];
            g_M2[t] = s;
        } else if (t < 6) {                  // c2[j]
            int j = t - 4;
            float s = 0.f;
            #pragma unroll
            for (int q = 0; q < 16; q++) s += b1[q] * W2[q * 2 + j];
            g_c2[j] = s;
        } else if (t < 14) {                 // MA[i*4+j]
            int u = t - 6, i = u >> 2, j = u & 3;
            float s = 0.f;
            #pragma unroll
            for (int q = 0; q < 16; q++) s += W1[i * 16 + q] * We[q * 4 + j];
            g_MA[u] = s;
        } else if (t < 18) {                 // cA[j]
            int j = t - 14;
            float s = 0.f;
            #pragma unroll
            for (int q = 0; q < 16; q++) s += b1[q] * We[q * 4 + j];
            g_cA[j] = s;
        } else if (t < 26) {                 // MB[i*4+j]
            int u = t - 18, i = u >> 2, j = u & 3;
            float s = 0.f;
            #pragma unroll
            for (int q = 0; q < 16; q++) s += W1[i * 16 + q] * We[(17 + q) * 4 + j];
            g_MB[u] = s;
        } else if (t < 30) {                 // cB[j]
            int j = t - 26;
            float s = 0.f;
            #pragma unroll
            for (int q = 0; q < 16; q++) s += b1[q] * We[(17 + q) * 4 + j];
            g_cB[j] = s;
        }
    }
}

// ---------------- K1: build padded CSR (1 int atomic per edge) ---------------
__global__ void k_build(const void* __restrict__ ei, int E) {
    int e = blockIdx.x * blockDim.x + threadIdx.x;
    if (e >= E) return;
    int is64 = g_idx64;
    int r = load_idx(ei, e, is64);
    int c = load_idx(ei, (long long)E + e, is64);
    int p = atomicAdd(&g_cursor[c], 1);
    if (p < c * PAD + PAD) g_csr[p] = r;
}

// ---------------- K2: per-node dinv + y = x*dinv -----------------------------
__global__ void k_node1(const float* __restrict__ x, int n) {
    int v = blockIdx.x * blockDim.x + threadIdx.x;
    if (v >= n) return;
    int deg = g_cursor[v] - v * PAD;
    float dinv = rsqrtf((float)(deg + 1));
    g_dinv[v] = dinv;
    float2 xv = ((const float2*)x)[v];
    g_y[v] = make_float2(xv.x * dinv, xv.y * dinv);
}

// ---------------- K3: aggregate y (2-dim), quarter-warp per node -------------
// 8 lanes per node: E[ceil(deg/8)] ~ 4.5 iterations (12% slot waste vs 50% at
// 32 lanes), 3-level butterfly, 2-way unrolled gather loop for MLP=2.
__global__ void k_agg1(int n) {
    int t = threadIdx.x;
    int idx = (blockIdx.x * blockDim.x + t) >> 3;
    int gl = t & 7;
    int v = min(idx, n - 1);
    bool valid = idx < n;
    int start = v * PAD;
    int end = valid ? min(g_cursor[v], start + PAD) : start;

    float dv = g_dinv[v];
    float2 yv = g_y[v];

    float ax = 0.f, ay = 0.f;
    int p = start + gl;
    for (; p + 8 < end; p += 16) {
        int s0 = __ldg(&g_csr[p]);
        int s1 = __ldg(&g_csr[p + 8]);
        float2 y0 = g_y[s0];
        float2 y1 = g_y[s1];
        ax += y0.x + y1.x;
        ay += y0.y + y1.y;
    }
    if (p < end) {
        float2 y0 = g_y[__ldg(&g_csr[p])];
        ax += y0.x; ay += y0.y;
    }
    #pragma unroll
    for (int off = 4; off; off >>= 1) {       // stays inside the 8-lane group
        ax += __shfl_xor_sync(0xffffffffu, ax, off);
        ay += __shfl_xor_sync(0xffffffffu, ay, off);
    }

    if (gl == 0 && valid) {
        ax += yv.x; ay += yv.y;               // self-loop
        float d2 = dv * dv;
        float2 s2;
        s2.x = d2 * (ax * g_M2[0] + ay * g_M2[2]) + dv * g_c2[0];
        s2.y = d2 * (ax * g_M2[1] + ay * g_M2[3]) + dv * g_c2[1];
        g_s2[v] = s2;
        float4 pa, pb;
        pa.x = dv * (ax * g_MA[0] + ay * g_MA[4]) + g_cA[0];
        pa.y = dv * (ax * g_MA[1] + ay * g_MA[5]) + g_cA[1];
        pa.z = dv * (ax * g_MA[2] + ay * g_MA[6]) + g_cA[2];
        pa.w = dv * (ax * g_MA[3] + ay * g_MA[7]) + g_cA[3];
        g_pA[v] = pa;
        pb.x = dv * (ax * g_MB[0] + ay * g_MB[4]) + g_cB[0];
        pb.y = dv * (ax * g_MB[1] + ay * g_MB[5]) + g_cB[1];
        pb.z = dv * (ax * g_MB[2] + ay * g_MB[6]) + g_cB[2];
        pb.w = dv * (ax * g_MB[3] + ay * g_MB[7]) + g_cB[3];
        g_pB[v] = pb;
    }
}

// ---------------- K4: FUSED tail -------------------------------------------
// blocks [0, edgeBlocks): edge MLP, 2 edges per thread, vectorized loads.
// blocks [edgeBlocks, ..): layer-2 aggregate + node softmax, 8 lanes per node.
__global__ void k_tail(const void* __restrict__ ei, const float* __restrict__ ea,
                       const float* __restrict__ We, const float* __restrict__ be,
                       const float* __restrict__ b2,
                       float* __restrict__ outN, float* __restrict__ outE,
                       int n, int E, int edgeBlocks) {
    int t = threadIdx.x;
    if ((int)blockIdx.x < edgeBlocks) {
        int i = blockIdx.x * blockDim.x + t;     // pair index
        int e0 = 2 * i;
        if (e0 >= E) return;
        int is64 = g_idx64;
        int r0, r1, c0, c1;
        if (is64) {
            longlong2 rr = __ldg(((const longlong2*)ei) + i);
            longlong2 cc = __ldg((const longlong2*)((const long long*)ei + E) + i);
            r0 = (int)rr.x; r1 = (int)rr.y; c0 = (int)cc.x; c1 = (int)cc.y;
        } else {
            int2 rr = __ldg(((const int2*)ei) + i);
            int2 cc = __ldg((const int2*)((const int*)ei + E) + i);
            r0 = rr.x; r1 = rr.y; c0 = cc.x; c1 = cc.y;
        }
        float2 aa = __ldg(((const float2*)ea) + i);
        float4 pa0 = g_pA[r0];
        float4 pb0 = g_pB[c0];
        float4 pa1 = g_pA[r1];
        float4 pb1 = g_pB[c1];
        float w0 = __ldg(&We[64 + 0]), w1 = __ldg(&We[64 + 1]);
        float w2 = __ldg(&We[64 + 2]), w3 = __ldg(&We[64 + 3]);
        float q0 = __ldg(&be[0]), q1 = __ldg(&be[1]);
        float q2 = __ldg(&be[2]), q3 = __ldg(&be[3]);
        {
            float t0 = fmaxf(pa0.x + pb0.x + aa.x * w0 + q0, 0.f);
            float t1 = fmaxf(pa0.y + pb0.y + aa.x * w1 + q1, 0.f);
            float t2 = fmaxf(pa0.z + pb0.z + aa.x * w2 + q2, 0.f);
            float t3 = fmaxf(pa0.w + pb0.w + aa.x * w3 + q3, 0.f);
            float m = fmaxf(fmaxf(t0, t1), fmaxf(t2, t3));
            float s = expf(t0 - m) + expf(t1 - m) + expf(t2 - m) + expf(t3 - m);
            float l = m + logf(s);
            ((float4*)outE)[e0] = make_float4(t0 - l, t1 - l, t2 - l, t3 - l);
        }
        if (e0 + 1 < E) {
            float t0 = fmaxf(pa1.x + pb1.x + aa.y * w0 + q0, 0.f);
            float t1 = fmaxf(pa1.y + pb1.y + aa.y * w1 + q1, 0.f);
            float t2 = fmaxf(pa1.z + pb1.z + aa.y * w2 + q2, 0.f);
            float t3 = fmaxf(pa1.w + pb1.w + aa.y * w3 + q3, 0.f);
            float m = fmaxf(fmaxf(t0, t1), fmaxf(t2, t3));
            float s = expf(t0 - m) + expf(t1 - m) + expf(t2 - m) + expf(t3 - m);
            float l = m + logf(s);
            ((float4*)outE)[e0 + 1] = make_float4(t0 - l, t1 - l, t2 - l, t3 - l);
        }
    } else {
        int idx = ((blockIdx.x - edgeBlocks) * blockDim.x + t) >> 3;
        int gl = t & 7;
        int v = min(idx, n - 1);
        bool valid = idx < n;
        int start = v * PAD;
        int end = valid ? min(g_cursor[v], start + PAD) : start;
        float dv = g_dinv[v];
        float2 sv = g_s2[v];
        float a0 = 0.f, a1 = 0.f;
        int p = start + gl;
        for (; p + 8 < end; p += 16) {
            float2 s0 = g_s2[__ldg(&g_csr[p])];
            float2 s1 = g_s2[__ldg(&g_csr[p + 8])];
            a0 += s0.x + s1.x;
            a1 += s0.y + s1.y;
        }
        if (p < end) {
            float2 s0 = g_s2[__ldg(&g_csr[p])];
            a0 += s0.x; a1 += s0.y;
        }
        #pragma unroll
        for (int off = 4; off; off >>= 1) {
            a0 += __shfl_xor_sync(0xffffffffu, a0, off);
            a1 += __shfl_xor_sync(0xffffffffu, a1, off);
        }
        if (gl == 0 && valid) {
            float o0 = dv * (a0 + sv.x) + __ldg(&b2[0]);
            float o1 = dv * (a1 + sv.y) + __ldg(&b2[1]);
            float m = fmaxf(o0, o1);
            float l = logf(expf(o0 - m) + expf(o1 - m));
            ((float2*)outN)[v] = make_float2(o0 - m - l, o1 - m - l);
        }
    }
}

// ---------------- launch ------------------------------------------------------
extern "C" void kernel_launch(void* const* d_in, const int* in_sizes, int n_in,
                              void* d_out, int out_size) {
    const float* x  = (const float*)d_in[0];
    const void*  ei = d_in[1];
    const float* ea = (const float*)d_in[2];
    const float* W1 = (const float*)d_in[3];
    const float* b1 = (const float*)d_in[4];
    const float* We = (const float*)d_in[5];
    const float* be = (const float*)d_in[6];
    const float* W2 = (const float*)d_in[7];
    const float* b2 = (const float*)d_in[8];

    int n = in_sizes[0] / 2;
    int E = in_sizes[1] / 2;
    float* outN = (float*)d_out;
    float* outE = outN + 2 * (size_t)n;

    const int TB = 256;
    int edgeBlocks = (E + 2 * TB - 1) / (2 * TB);          // 2 edges per thread
    int nodeBlocks8 = (8 * n + TB - 1) / TB;               // 8 lanes per node

    k_init  <<<(n + TB - 1) / TB, TB>>>((const int*)ei, n, W1, b1, We, W2);
    k_build <<<(E + TB - 1) / TB, TB>>>(ei, E);
    k_node1 <<<(n + TB - 1) / TB, TB>>>(x, n);
    k_agg1  <<<nodeBlocks8, TB>>>(n);
    k_tail  <<<edgeBlocks + nodeBlocks8, TB>>>(ei, ea, We, be, b2, outN, outE, n, E, edgeBlocks);
}